// round 16
// baseline (speedup 1.0000x reference)
#include <cuda_runtime.h>
#include <math.h>
#include <stdint.h>

#define K_CODES   8192
#define CDIM      256
#define NQ        32768
#define OUT_ELEMS 8388608

#define MT 128                 // M per CTA
#define NT 128                 // N per CTA tile
#define KC 32                  // K per chunk
#define PADR 36                // smem row stride (floats): 32 + 4
#define N_TILES (K_CODES/NT)   // 64
#define K_CHUNKS (CDIM/KC)     // 8
#define TOT_CHUNKS (N_TILES*K_CHUNKS)  // 512
#define THREADS 256
#define STAGES 3

// smem float offsets (hi-only, single pass)
#define AHI_F 0
#define BHI_F 4608             // 128*36
#define STAGE_F 9216           // 4608 + 128*36
#define SMEM_BYTES (STAGES * STAGE_F * 4)   // 110592 -> 2 CTAs/SM

__device__ float  g_ahi[(size_t)NQ * CDIM];      // tf32(z), k-permuted
__device__ float  g_zt [(size_t)NQ * CDIM];      // exact z, transposed [n][c]
__device__ float  g_bhi[(size_t)K_CODES * CDIM]; // tf32(cn), k-permuted
__device__ float  g_cn [(size_t)K_CODES * CDIM]; // exact cn, natural order
__device__ int4   g_candi[NQ];
__device__ int    g_idx[NQ];
__device__ double g_acc;

// within-8 k permutation: pos = 2*(k&3) + ((k>>2)&1)  -> (k, k+4) adjacent
__device__ __forceinline__ int kperm(int k) {
    return (k & ~7) | (((k & 3) << 1) | ((k >> 2) & 1));
}

// ---------------------------------------------------------------------------
__device__ __forceinline__ void cp16(uint32_t dst, const void* src) {
    asm volatile("cp.async.cg.shared.global [%0], [%1], 16;" :: "r"(dst), "l"(src));
}
#define CP_COMMIT()  asm volatile("cp.async.commit_group;" ::: "memory")
#define CP_WAIT(N)   asm volatile("cp.async.wait_group %0;" :: "n"(N) : "memory")

__device__ __forceinline__ uint32_t smem_u32(const void* p) {
    uint32_t a;
    asm("{ .reg .u64 t; cvta.to.shared.u64 t, %1; cvt.u32.u64 %0, t; }"
        : "=r"(a) : "l"(p));
    return a;
}

#define LDSV2U(x, y, a) \
    asm volatile("ld.shared.v2.u32 {%0,%1}, [%2];" : "=r"(x), "=r"(y) : "r"(a))

#define MMA_TF32(d, a, b) \
    asm volatile("mma.sync.aligned.m16n8k8.row.col.f32.tf32.tf32.f32 " \
        "{%0,%1,%2,%3}, {%4,%5,%6,%7}, {%8,%9}, {%0,%1,%2,%3};" \
        : "+f"((d)[0]), "+f"((d)[1]), "+f"((d)[2]), "+f"((d)[3]) \
        : "r"((a)[0]), "r"((a)[1]), "r"((a)[2]), "r"((a)[3]), \
          "r"((b)[0]), "r"((b)[1]))

__device__ __forceinline__ float tf32val(float x) {
    uint32_t h;
    asm("cvt.rna.tf32.f32 %0, %1;" : "=r"(h) : "f"(x));
    return __uint_as_float(h);
}

__device__ __forceinline__ bool better(float v, int i, float V, int I) {
    return (v > V) || (v == V && i < I);
}
__device__ __forceinline__ void ins3(float v, int i, float* V, int* I) {
    if (better(v, i, V[0], I[0])) {
        V[2]=V[1]; I[2]=I[1]; V[1]=V[0]; I[1]=I[0]; V[0]=v; I[0]=i;
    } else if (better(v, i, V[1], I[1])) {
        V[2]=V[1]; I[2]=I[1]; V[1]=v; I[1]=i;
    } else if (better(v, i, V[2], I[2])) {
        V[2]=v; I[2]=i;
    }
}

// ---------------------------------------------------------------------------
__global__ void zero_acc_kernel() { g_acc = 0.0; }

// Transpose z [B,C,H,W] -> A [n][c]: tf32 k-permuted (g_ahi) + exact (g_zt).
__global__ void split_z_kernel(const float* __restrict__ z) {
    __shared__ float th[32][33];
    __shared__ float tx[32][33];
    int tid = threadIdx.x;
    int hw0 = blockIdx.x * 32, c0 = blockIdx.y * 32, b = blockIdx.z;
#pragma unroll
    for (int i = 0; i < 4; i++) {
        int e = tid + i * 256;
        int cc = e >> 5, hh = e & 31;
        float x = z[(size_t)b * 262144 + (size_t)(c0 + cc) * 1024 + hw0 + hh];
        th[cc][hh] = tf32val(x);
        tx[cc][hh] = x;
    }
    __syncthreads();
#pragma unroll
    for (int i = 0; i < 4; i++) {
        int e = tid + i * 256;
        int hh = e >> 5, cc = e & 31;
        size_t n = (size_t)(b * 1024 + hw0 + hh);
        g_ahi[n * CDIM + kperm(c0 + cc)] = th[cc][hh];
        g_zt [n * CDIM + c0 + cc]        = tx[cc][hh];
    }
}

// Normalize codebook rows; store exact cn (natural) + tf32 (k-permuted).
__global__ void norm_split_codebook(const float* __restrict__ E) {
    int row  = blockIdx.x * 8 + (threadIdx.x >> 5);
    int lane = threadIdx.x & 31;
    const float4* r4 = (const float4*)(E + (size_t)row * CDIM);
    float4 v0 = r4[lane];
    float4 v1 = r4[lane + 32];
    float ss = v0.x*v0.x + v0.y*v0.y + v0.z*v0.z + v0.w*v0.w
             + v1.x*v1.x + v1.y*v1.y + v1.z*v1.z + v1.w*v1.w;
#pragma unroll
    for (int off = 16; off; off >>= 1)
        ss += __shfl_xor_sync(0xffffffffu, ss, off);
    float s = 1.0f / fmaxf(sqrtf(ss), 1e-12f);
    float xs[8] = {v0.x*s, v0.y*s, v0.z*s, v0.w*s, v1.x*s, v1.y*s, v1.z*s, v1.w*s};
    float4* oc = (float4*)(g_cn + (size_t)row * CDIM);
    oc[lane]      = make_float4(xs[0], xs[1], xs[2], xs[3]);
    oc[lane + 32] = make_float4(xs[4], xs[5], xs[6], xs[7]);
    float* oh = g_bhi + (size_t)row * CDIM;
#pragma unroll
    for (int j = 0; j < 8; j++) {
        int k = (j < 4) ? (lane * 4 + j) : (128 + lane * 4 + j - 4);
        oh[kperm(k)] = tf32val(xs[j]);
    }
}

// ---------------------------------------------------------------------------
// Chunk body, stage S compile-time. Consumes stage S, prefetches it+2 into
// (S+2)%3, folds top-3 at N-tile boundary. All stage addressing constant.
struct VqState {
    uint32_t sA[STAGES], sB[STAGES];   // smem byte bases for cp16 per stage
    uint32_t fA[STAGES], fB[STAGES];   // smem byte fragment bases per stage
    uint32_t soff[4];                  // per-thread cp16 smem offsets (bytes)
    int      goff[4];                  // per-thread cp16 global offsets (floats)
    const float* pAb;                  // prefetch global ptr (chunk it+2), A
    const float* pBb;                  // prefetch global ptr (chunk it+2), B
};

template<int S>
__device__ __forceinline__ void chunk_body(
    int it, VqState& st,
    float (&acc)[2][8][4], float (&r3v)[4][3], int (&r3i)[4][3],
    int wn, int tig)
{
    CP_WAIT(1);
    __syncthreads();

    uint32_t aB = st.fA[S];
    uint32_t bB = st.fB[S];
#pragma unroll
    for (int k8 = 0; k8 < 4; k8++) {
        const uint32_t kb = k8 * 8 * 4;     // byte offset
        uint32_t ah[2][4], bh[8][2];
#pragma unroll
        for (int mf = 0; mf < 2; mf++) {
            LDSV2U(ah[mf][0], ah[mf][2], aB + mf * (16 * PADR * 4) + kb);
            LDSV2U(ah[mf][1], ah[mf][3], aB + mf * (16 * PADR * 4) + 8 * PADR * 4 + kb);
        }
#pragma unroll
        for (int nf = 0; nf < 8; nf++)
            LDSV2U(bh[nf][0], bh[nf][1], bB + nf * (8 * PADR * 4) + kb);
#pragma unroll
        for (int mf = 0; mf < 2; mf++)
#pragma unroll
            for (int nf = 0; nf < 8; nf++)
                MMA_TF32(acc[mf][nf], ah[mf], bh[nf]);
    }

    // prefetch chunk it+2 into stage (S+2)%3
    if (it + 2 < TOT_CHUNKS) {
        constexpr int PS = (S + 2) % STAGES;
#pragma unroll
        for (int i = 0; i < 4; i++) {
            cp16(st.sA[PS] + st.soff[i], st.pAb + st.goff[i]);
            cp16(st.sB[PS] + st.soff[i], st.pBb + st.goff[i]);
        }
    }
    CP_COMMIT();
    // advance prefetch pointers to chunk it+3
    if ((it & 7) == 5) {            // (it+2) ends an nt: wrap
        st.pAb -= 224;              // +32 - 256
        st.pBb += NT * CDIM - 224;
    } else {
        st.pAb += 32;
        st.pBb += 32;
    }

    // end of an N-tile: fold acc into running top-3, reset acc
    if ((it & 7) == 7) {
        int base = (it >> 3) * NT + wn * 64 + 2 * tig;
#pragma unroll
        for (int mf = 0; mf < 2; mf++) {
#pragma unroll
            for (int half = 0; half < 2; half++) {
                int rg = mf * 2 + half;
#pragma unroll
                for (int nf = 0; nf < 8; nf++) {
#pragma unroll
                    for (int p = 0; p < 2; p++) {
                        float v = acc[mf][nf][half * 2 + p];
                        if (v > r3v[rg][2]) {
                            ins3(v, base + nf * 8 + p, r3v[rg], r3i[rg]);
                        }
                    }
                }
            }
        }
#pragma unroll
        for (int mf = 0; mf < 2; mf++)
#pragma unroll
            for (int nf = 0; nf < 8; nf++)
#pragma unroll
                for (int q = 0; q < 4; q++) acc[mf][nf][q] = 0.0f;
    }
}

// ---------------------------------------------------------------------------
// Single-pass tf32 HMMA GEMM + per-thread running top-3 (merged once at end).
// 8 warps (4x2 grid of 32x64 tiles), 3-stage cp.async ring (dist 2),
// stage-constant addressing via unroll-by-3, 2 CTAs/SM.
__global__ __launch_bounds__(THREADS, 2)
void vq_mma_kernel() {
    extern __shared__ float smem[];
    uint32_t smem_b = smem_u32(smem);
    int tid = threadIdx.x;
    int wid = tid >> 5, lane = tid & 31;
    int gid = lane >> 2, tig = lane & 3;
    int wm = wid >> 1, wn = wid & 1;     // 4x2 warp grid: 32-row x 64-col tiles
    int mBlk = blockIdx.x * MT;

    VqState st;
#pragma unroll
    for (int s = 0; s < STAGES; s++) {
        st.sA[s] = smem_b + (s * STAGE_F + AHI_F) * 4;
        st.sB[s] = smem_b + (s * STAGE_F + BHI_F) * 4;
        st.fA[s] = smem_b + (s * STAGE_F + AHI_F + (wm * 32 + gid) * PADR + 2 * tig) * 4;
        st.fB[s] = smem_b + (s * STAGE_F + BHI_F + (wn * 64 + gid) * PADR + 2 * tig) * 4;
    }
#pragma unroll
    for (int i = 0; i < 4; i++) {
        int f = tid + i * THREADS;
        int r = f >> 3, c4 = (f & 7) << 2;
        st.soff[i] = (uint32_t)(r * PADR + c4) * 4;
        st.goff[i] = r * CDIM + c4;
    }
    const float* Abase = g_ahi + (size_t)mBlk * CDIM;

    float r3v[4][3];
    int   r3i[4][3];
#pragma unroll
    for (int rg = 0; rg < 4; rg++)
#pragma unroll
        for (int e = 0; e < 3; e++) { r3v[rg][e] = -INFINITY; r3i[rg][e] = 0x7fffffff; }

    // prologue: chunks 0 and 1 into stages 0 and 1
#pragma unroll
    for (int i = 0; i < 4; i++)
        { cp16(st.sA[0] + st.soff[i], Abase + st.goff[i]);
          cp16(st.sB[0] + st.soff[i], g_bhi + st.goff[i]); }
    CP_COMMIT();
#pragma unroll
    for (int i = 0; i < 4; i++)
        { cp16(st.sA[1] + st.soff[i], Abase + 32 + st.goff[i]);
          cp16(st.sB[1] + st.soff[i], g_bhi + 32 + st.goff[i]); }
    CP_COMMIT();

    st.pAb = Abase + 64;          // chunk 2: nt=0, ct=2
    st.pBb = g_bhi + 64;

    float acc[2][8][4];
#pragma unroll
    for (int mf = 0; mf < 2; mf++)
#pragma unroll
        for (int nf = 0; nf < 8; nf++)
#pragma unroll
            for (int q = 0; q < 4; q++) acc[mf][nf][q] = 0.0f;

#pragma unroll 1
    for (int it3 = 0; it3 < TOT_CHUNKS - 2; it3 += 3) {
        chunk_body<0>(it3 + 0, st, acc, r3v, r3i, wn, tig);
        chunk_body<1>(it3 + 1, st, acc, r3v, r3i, wn, tig);
        chunk_body<2>(it3 + 2, st, acc, r3v, r3i, wn, tig);
    }
    chunk_body<0>(TOT_CHUNKS - 2, st, acc, r3v, r3i, wn, tig);
    chunk_body<1>(TOT_CHUNKS - 1, st, acc, r3v, r3i, wn, tig);

    // ---- one-time final merge ----
#pragma unroll
    for (int rg = 0; rg < 4; rg++) {
#pragma unroll
        for (int off = 1; off <= 2; off <<= 1) {
            float ov[3]; int oi[3];
#pragma unroll
            for (int e = 0; e < 3; e++) {
                ov[e] = __shfl_xor_sync(0xffffffffu, r3v[rg][e], off);
                oi[e] = __shfl_xor_sync(0xffffffffu, r3i[rg][e], off);
            }
#pragma unroll
            for (int e = 0; e < 3; e++) ins3(ov[e], oi[e], r3v[rg], r3i[rg]);
        }
    }
    __syncthreads();   // mainloop fully done; stage area becomes scratch
    float* scr_v = (float*)smem;            // [128 rows][2 wn][3]
    int*   scr_i = (int*)(smem + 1024);
    if (tig == 0) {
#pragma unroll
        for (int rg = 0; rg < 4; rg++) {
            int mf = rg >> 1, half = rg & 1;
            int rl = wm * 32 + mf * 16 + half * 8 + gid;
#pragma unroll
            for (int e = 0; e < 3; e++) {
                scr_v[(rl * 2 + wn) * 3 + e] = r3v[rg][e];
                scr_i[(rl * 2 + wn) * 3 + e] = r3i[rg][e];
            }
        }
    }
    __syncthreads();
    if (tid < 128) {
        float fv[3] = {-INFINITY, -INFINITY, -INFINITY};
        int   fi[3] = {0x7fffffff, 0x7fffffff, 0x7fffffff};
#pragma unroll
        for (int w = 0; w < 2; w++)
#pragma unroll
            for (int e = 0; e < 3; e++)
                ins3(scr_v[(tid * 2 + w) * 3 + e],
                     scr_i[(tid * 2 + w) * 3 + e], fv, fi);
        g_candi[mBlk + tid] = make_int4(fi[0], fi[1], fi[2], 0);
    }
}

// ---------------------------------------------------------------------------
// Warp-per-row exact fp32 rescore of 3 candidates (all rows coalesced).
__global__ void fixup_kernel(float* __restrict__ idx_out_f) {
    int n = (blockIdx.x * blockDim.x + threadIdx.x) >> 5;
    int lane = threadIdx.x & 31;
    int4 cd = g_candi[n];
    const float4* zr = (const float4*)(g_zt + (size_t)n * CDIM);
    const float4* c0 = (const float4*)(g_cn + (size_t)cd.x * CDIM);
    const float4* c1 = (const float4*)(g_cn + (size_t)cd.y * CDIM);
    const float4* c2 = (const float4*)(g_cn + (size_t)cd.z * CDIM);
    float d0 = 0.0f, d1 = 0.0f, d2 = 0.0f;
#pragma unroll
    for (int i = 0; i < 2; i++) {
        float4 zv = zr[lane + i * 32];
        float4 a  = c0[lane + i * 32];
        float4 b  = c1[lane + i * 32];
        float4 c  = c2[lane + i * 32];
        d0 = fmaf(zv.x, a.x, fmaf(zv.y, a.y, fmaf(zv.z, a.z, fmaf(zv.w, a.w, d0))));
        d1 = fmaf(zv.x, b.x, fmaf(zv.y, b.y, fmaf(zv.z, b.z, fmaf(zv.w, b.w, d1))));
        d2 = fmaf(zv.x, c.x, fmaf(zv.y, c.y, fmaf(zv.z, c.z, fmaf(zv.w, c.w, d2))));
    }
#pragma unroll
    for (int off = 16; off; off >>= 1) {
        d0 += __shfl_xor_sync(0xffffffffu, d0, off);
        d1 += __shfl_xor_sync(0xffffffffu, d1, off);
        d2 += __shfl_xor_sync(0xffffffffu, d2, off);
    }
    if (lane == 0) {
        float bv = d0; int bi = cd.x;
        if (better(d1, cd.y, bv, bi)) { bv = d1; bi = cd.y; }
        if (better(d2, cd.z, bv, bi)) { bv = d2; bi = cd.z; }
        g_idx[n] = bi;
        idx_out_f[n] = (float)bi;
    }
}

// ---------------------------------------------------------------------------
// Gather + straight-through output + loss, fully coalesced via smem transpose.
// CTA handles one (b, 32-wide hw block): tile [256 c][32 hw].
__global__ void gather_loss_kernel(const float* __restrict__ z,
                                   const float* __restrict__ E,
                                   float* __restrict__ out) {
    __shared__ float q[256 * 33];
    int tid = threadIdx.x;
    int wid = tid >> 5, lane = tid & 31;
    int b = blockIdx.x >> 5;
    int hw0 = (blockIdx.x & 31) * 32;

    // phase 1: gather codebook rows (coalesced) into transposed smem tile
#pragma unroll
    for (int r = 0; r < 4; r++) {
        int hh = wid * 4 + r;
        int n  = b * 1024 + hw0 + hh;
        int k  = g_idx[n];
        const float4* Er = (const float4*)(E + (size_t)k * CDIM);
#pragma unroll
        for (int i = 0; i < 2; i++) {
            int c4 = (lane + i * 32) * 4;
            float4 v = Er[lane + i * 32];
            q[(c4 + 0) * 33 + hh] = v.x;
            q[(c4 + 1) * 33 + hh] = v.y;
            q[(c4 + 2) * 33 + hh] = v.z;
            q[(c4 + 3) * 33 + hh] = v.w;
        }
    }
    __syncthreads();

    // phase 2: coalesced z read / out write along hw; accumulate loss
    float d2sum = 0.0f;
    size_t gbase = (size_t)b * 262144 + hw0 + lane;
#pragma unroll 4
    for (int i = 0; i < 32; i++) {
        int c = wid * 32 + i;
        float qv = q[c * 33 + lane];
        float zv = z[gbase + (size_t)c * 1024];
        float d  = qv - zv;
        out[gbase + (size_t)c * 1024] = zv + d;
        d2sum = fmaf(d, d, d2sum);
    }
#pragma unroll
    for (int off = 16; off; off >>= 1)
        d2sum += __shfl_xor_sync(0xffffffffu, d2sum, off);
    __shared__ float ws[8];
    if (lane == 0) ws[wid] = d2sum;
    __syncthreads();
    if (wid == 0) {
        float s = (lane < 8) ? ws[lane] : 0.0f;
#pragma unroll
        for (int off = 4; off; off >>= 1)
            s += __shfl_xor_sync(0xffffffffu, s, off);
        if (lane == 0) atomicAdd(&g_acc, (double)s);
    }
}

// ---------------------------------------------------------------------------
__global__ void finalize_kernel(float* __restrict__ out) {
    double m = g_acc / (double)OUT_ELEMS;
    out[OUT_ELEMS] = (float)(0.25 * m + m);
}

// ---------------------------------------------------------------------------
extern "C" void kernel_launch(void* const* d_in, const int* in_sizes, int n_in,
                              void* d_out, int out_size) {
    const float* z = (const float*)d_in[0];
    const float* E = (const float*)d_in[1];
    float* out = (float*)d_out;

    cudaFuncSetAttribute(vq_mma_kernel,
                         cudaFuncAttributeMaxDynamicSharedMemorySize, SMEM_BYTES);

    zero_acc_kernel<<<1, 1>>>();
    split_z_kernel<<<dim3(32, 8, 32), 256>>>(z);
    norm_split_codebook<<<K_CODES / 8, 256>>>(E);
    vq_mma_kernel<<<NQ / MT, THREADS, SMEM_BYTES>>>();
    fixup_kernel<<<NQ / 8, 256>>>(out + OUT_ELEMS + 1);
    gather_loss_kernel<<<1024, 256>>>(z, E, out);
    finalize_kernel<<<1, 1>>>(out);
}

// round 17
// speedup vs baseline: 1.0578x; 1.0578x over previous
#include <cuda_runtime.h>
#include <math.h>
#include <stdint.h>

#define K_CODES   8192
#define CDIM      256
#define NQ        32768
#define OUT_ELEMS 8388608

#define MT 128                 // M per CTA
#define NT 128                 // N per CTA tile
#define KC 32                  // K per chunk
#define PADR 36                // smem row stride (floats): 32 + 4
#define N_TILES (K_CODES/NT)   // 64
#define K_CHUNKS (CDIM/KC)     // 8
#define TOT_CHUNKS (N_TILES*K_CHUNKS)  // 512
#define THREADS 256
#define STAGES 3

// smem float offsets (hi-only, single pass)
#define AHI_F 0
#define BHI_F 4608             // 128*36
#define STAGE_F 9216           // 4608 + 128*36
#define SMEM_BYTES (STAGES * STAGE_F * 4)   // 110592 -> 2 CTAs/SM

__device__ float  g_ahi[(size_t)NQ * CDIM];      // tf32(z), k-permuted
__device__ float  g_zt [(size_t)NQ * CDIM];      // exact z, transposed [n][c]
__device__ float  g_bhi[(size_t)K_CODES * CDIM]; // tf32(cn), k-permuted
__device__ float  g_cn [(size_t)K_CODES * CDIM]; // exact cn, natural order
__device__ int4   g_candi[NQ];
__device__ int    g_idx[NQ];
__device__ double g_acc;
__device__ unsigned int g_ticket;

// within-8 k permutation: pos = 2*(k&3) + ((k>>2)&1)  -> (k, k+4) adjacent
__device__ __forceinline__ int kperm(int k) {
    return (k & ~7) | (((k & 3) << 1) | ((k >> 2) & 1));
}

// ---------------------------------------------------------------------------
__device__ __forceinline__ void cp16(uint32_t dst, const void* src) {
    asm volatile("cp.async.cg.shared.global [%0], [%1], 16;" :: "r"(dst), "l"(src));
}
#define CP_COMMIT()  asm volatile("cp.async.commit_group;" ::: "memory")
#define CP_WAIT(N)   asm volatile("cp.async.wait_group %0;" :: "n"(N) : "memory")

__device__ __forceinline__ uint32_t smem_u32(const void* p) {
    uint32_t a;
    asm("{ .reg .u64 t; cvta.to.shared.u64 t, %1; cvt.u32.u64 %0, t; }"
        : "=r"(a) : "l"(p));
    return a;
}

#define MMA_TF32(d, a, b) \
    asm volatile("mma.sync.aligned.m16n8k8.row.col.f32.tf32.tf32.f32 " \
        "{%0,%1,%2,%3}, {%4,%5,%6,%7}, {%8,%9}, {%0,%1,%2,%3};" \
        : "+f"((d)[0]), "+f"((d)[1]), "+f"((d)[2]), "+f"((d)[3]) \
        : "r"((a)[0]), "r"((a)[1]), "r"((a)[2]), "r"((a)[3]), \
          "r"((b)[0]), "r"((b)[1]))

__device__ __forceinline__ float tf32val(float x) {
    uint32_t h;
    asm("cvt.rna.tf32.f32 %0, %1;" : "=r"(h) : "f"(x));
    return __uint_as_float(h);
}

__device__ __forceinline__ bool better(float v, int i, float V, int I) {
    return (v > V) || (v == V && i < I);
}
__device__ __forceinline__ void ins3(float v, int i, float* V, int* I) {
    if (better(v, i, V[0], I[0])) {
        V[2]=V[1]; I[2]=I[1]; V[1]=V[0]; I[1]=I[0]; V[0]=v; I[0]=i;
    } else if (better(v, i, V[1], I[1])) {
        V[2]=V[1]; I[2]=I[1]; V[1]=v; I[1]=i;
    } else if (better(v, i, V[2], I[2])) {
        V[2]=v; I[2]=i;
    }
}

// ---------------------------------------------------------------------------
// Transpose z [B,C,H,W] -> A [n][c]: tf32 k-permuted (g_ahi) + exact (g_zt).
// Block (0,0,0) thread 0 also resets the accumulator + ticket.
__global__ void split_z_kernel(const float* __restrict__ z) {
    __shared__ float th[32][33];
    __shared__ float tx[32][33];
    int tid = threadIdx.x;
    int hw0 = blockIdx.x * 32, c0 = blockIdx.y * 32, b = blockIdx.z;
    if (tid == 0 && blockIdx.x == 0 && blockIdx.y == 0 && blockIdx.z == 0) {
        g_acc = 0.0;
        g_ticket = 0u;
    }
#pragma unroll
    for (int i = 0; i < 4; i++) {
        int e = tid + i * 256;
        int cc = e >> 5, hh = e & 31;
        float x = z[(size_t)b * 262144 + (size_t)(c0 + cc) * 1024 + hw0 + hh];
        th[cc][hh] = tf32val(x);
        tx[cc][hh] = x;
    }
    __syncthreads();
#pragma unroll
    for (int i = 0; i < 4; i++) {
        int e = tid + i * 256;
        int hh = e >> 5, cc = e & 31;
        size_t n = (size_t)(b * 1024 + hw0 + hh);
        g_ahi[n * CDIM + kperm(c0 + cc)] = th[cc][hh];
        g_zt [n * CDIM + c0 + cc]        = tx[cc][hh];
    }
}

// Normalize codebook rows; store exact cn (natural) + tf32 (k-permuted).
__global__ void norm_split_codebook(const float* __restrict__ E) {
    int row  = blockIdx.x * 8 + (threadIdx.x >> 5);
    int lane = threadIdx.x & 31;
    const float4* r4 = (const float4*)(E + (size_t)row * CDIM);
    float4 v0 = r4[lane];
    float4 v1 = r4[lane + 32];
    float ss = v0.x*v0.x + v0.y*v0.y + v0.z*v0.z + v0.w*v0.w
             + v1.x*v1.x + v1.y*v1.y + v1.z*v1.z + v1.w*v1.w;
#pragma unroll
    for (int off = 16; off; off >>= 1)
        ss += __shfl_xor_sync(0xffffffffu, ss, off);
    float s = 1.0f / fmaxf(sqrtf(ss), 1e-12f);
    float xs[8] = {v0.x*s, v0.y*s, v0.z*s, v0.w*s, v1.x*s, v1.y*s, v1.z*s, v1.w*s};
    float4* oc = (float4*)(g_cn + (size_t)row * CDIM);
    oc[lane]      = make_float4(xs[0], xs[1], xs[2], xs[3]);
    oc[lane + 32] = make_float4(xs[4], xs[5], xs[6], xs[7]);
    float* oh = g_bhi + (size_t)row * CDIM;
#pragma unroll
    for (int j = 0; j < 8; j++) {
        int k = (j < 4) ? (lane * 4 + j) : (128 + lane * 4 + j - 4);
        oh[kperm(k)] = tf32val(xs[j]);
    }
}

// ---------------------------------------------------------------------------
// it = nt*8 + ct : load A chunk (ct) and B chunk (nt, ct) into one stage.
__device__ __forceinline__ void load_chunk_it(uint32_t sb_addr, int tid,
                                              int mBlk, int it) {
    int nt = it >> 3, ct = it & 7;
    int co = ct * KC;
    const float* Ah = g_ahi + (size_t)mBlk * CDIM + co;
    const float* Bh = g_bhi + (size_t)nt * NT * CDIM + co;
#pragma unroll
    for (int i = 0; i < 4; i++) {
        int f = tid + i * THREADS;          // 0..1023: 128 rows x 8 float4
        int r = f >> 3, c4 = (f & 7) << 2;
        uint32_t so = (uint32_t)(r * PADR + c4) * 4;
        cp16(sb_addr + AHI_F * 4 + so, Ah + (size_t)r * CDIM + c4);
    }
#pragma unroll
    for (int i = 0; i < 4; i++) {
        int f = tid + i * THREADS;          // 0..1023: 128 rows x 8 float4
        int r = f >> 3, c4 = (f & 7) << 2;
        uint32_t so = (uint32_t)(r * PADR + c4) * 4;
        cp16(sb_addr + BHI_F * 4 + so, Bh + (size_t)r * CDIM + c4);
    }
}

// ---------------------------------------------------------------------------
// Single-pass tf32 HMMA GEMM + per-thread running top-3 (merged once at end).
// 8 warps (4x2 grid of 32x64 tiles), 3-stage cp.async ring (prefetch dist 2),
// prefetch AFTER the MMAs, 2 CTAs/SM. (R15-exact, measured 1.216 ms.)
__global__ __launch_bounds__(THREADS, 2)
void vq_mma_kernel() {
    extern __shared__ float smem[];
    uint32_t smem_b = smem_u32(smem);
    int tid = threadIdx.x;
    int wid = tid >> 5, lane = tid & 31;
    int gid = lane >> 2, tig = lane & 3;
    int wm = wid >> 1, wn = wid & 1;     // 4x2 warp grid: 32-row x 64-col tiles
    int mBlk = blockIdx.x * MT;

    float r3v[4][3];
    int   r3i[4][3];
#pragma unroll
    for (int rg = 0; rg < 4; rg++)
#pragma unroll
        for (int e = 0; e < 3; e++) { r3v[rg][e] = -INFINITY; r3i[rg][e] = 0x7fffffff; }

    // prologue: stages 0 and 1
    load_chunk_it(smem_b + 0 * STAGE_F * 4, tid, mBlk, 0);
    CP_COMMIT();
    load_chunk_it(smem_b + 1 * STAGE_F * 4, tid, mBlk, 1);
    CP_COMMIT();

    float acc[2][8][4];
#pragma unroll
    for (int mf = 0; mf < 2; mf++)
#pragma unroll
        for (int nf = 0; nf < 8; nf++)
#pragma unroll
            for (int q = 0; q < 4; q++) acc[mf][nf][q] = 0.0f;

    int stage = 0;
#pragma unroll 1
    for (int it = 0; it < TOT_CHUNKS; it++) {
        CP_WAIT(1);
        __syncthreads();

        const float* S = smem + stage * STAGE_F;
        const float* pAh = S + AHI_F + (wm*32 + gid) * PADR + 2*tig;
        const float* pBh = S + BHI_F + (wn*64 + gid) * PADR + 2*tig;
#pragma unroll
        for (int k8 = 0; k8 < 4; k8++) {
            int kb = k8 * 8;
            uint32_t ah[2][4], bh[8][2];
#pragma unroll
            for (int mf = 0; mf < 2; mf++) {
                float2 f1 = *(const float2*)(pAh + mf * (16 * PADR) + kb);
                float2 f2 = *(const float2*)(pAh + mf * (16 * PADR) + 8 * PADR + kb);
                ah[mf][0] = __float_as_uint(f1.x);
                ah[mf][1] = __float_as_uint(f2.x);
                ah[mf][2] = __float_as_uint(f1.y);
                ah[mf][3] = __float_as_uint(f2.y);
            }
#pragma unroll
            for (int nf = 0; nf < 8; nf++) {
                float2 f = *(const float2*)(pBh + nf * (8 * PADR) + kb);
                bh[nf][0] = __float_as_uint(f.x);
                bh[nf][1] = __float_as_uint(f.y);
            }
#pragma unroll
            for (int mf = 0; mf < 2; mf++)
#pragma unroll
                for (int nf = 0; nf < 8; nf++)
                    MMA_TF32(acc[mf][nf], ah[mf], bh[nf]);
        }

        // issue prefetch for it+2 into the stage consumed at it-1
        if (it + 2 < TOT_CHUNKS) {
            int ps = stage + 2; if (ps >= STAGES) ps -= STAGES;
            load_chunk_it(smem_b + ps * STAGE_F * 4, tid, mBlk, it + 2);
        }
        CP_COMMIT();

        // end of an N-tile: fold acc into running top-3, reset acc
        if ((it & 7) == 7) {
            int nt = it >> 3;
            int base = nt * NT + wn * 64 + 2 * tig;
#pragma unroll
            for (int mf = 0; mf < 2; mf++) {
#pragma unroll
                for (int half = 0; half < 2; half++) {
                    int rg = mf * 2 + half;
#pragma unroll
                    for (int nf = 0; nf < 8; nf++) {
#pragma unroll
                        for (int p = 0; p < 2; p++) {
                            float v = acc[mf][nf][half * 2 + p];
                            if (v > r3v[rg][2]) {
                                ins3(v, base + nf * 8 + p, r3v[rg], r3i[rg]);
                            }
                        }
                    }
                }
            }
#pragma unroll
            for (int mf = 0; mf < 2; mf++)
#pragma unroll
                for (int nf = 0; nf < 8; nf++)
#pragma unroll
                    for (int q = 0; q < 4; q++) acc[mf][nf][q] = 0.0f;
        }

        stage++; if (stage == STAGES) stage = 0;
    }

    // ---- one-time final merge ----
#pragma unroll
    for (int rg = 0; rg < 4; rg++) {
#pragma unroll
        for (int off = 1; off <= 2; off <<= 1) {
            float ov[3]; int oi[3];
#pragma unroll
            for (int e = 0; e < 3; e++) {
                ov[e] = __shfl_xor_sync(0xffffffffu, r3v[rg][e], off);
                oi[e] = __shfl_xor_sync(0xffffffffu, r3i[rg][e], off);
            }
#pragma unroll
            for (int e = 0; e < 3; e++) ins3(ov[e], oi[e], r3v[rg], r3i[rg]);
        }
    }
    __syncthreads();   // mainloop fully done; stage area becomes scratch
    float* scr_v = (float*)smem;            // [128 rows][2 wn][3]
    int*   scr_i = (int*)(smem + 1024);
    if (tig == 0) {
#pragma unroll
        for (int rg = 0; rg < 4; rg++) {
            int mf = rg >> 1, half = rg & 1;
            int rl = wm * 32 + mf * 16 + half * 8 + gid;
#pragma unroll
            for (int e = 0; e < 3; e++) {
                scr_v[(rl * 2 + wn) * 3 + e] = r3v[rg][e];
                scr_i[(rl * 2 + wn) * 3 + e] = r3i[rg][e];
            }
        }
    }
    __syncthreads();
    if (tid < 128) {
        float fv[3] = {-INFINITY, -INFINITY, -INFINITY};
        int   fi[3] = {0x7fffffff, 0x7fffffff, 0x7fffffff};
#pragma unroll
        for (int w = 0; w < 2; w++)
#pragma unroll
            for (int e = 0; e < 3; e++)
                ins3(scr_v[(tid * 2 + w) * 3 + e],
                     scr_i[(tid * 2 + w) * 3 + e], fv, fi);
        g_candi[mBlk + tid] = make_int4(fi[0], fi[1], fi[2], 0);
    }
}

// ---------------------------------------------------------------------------
// Warp-per-row exact fp32 rescore of 3 candidates (all rows coalesced).
__global__ void fixup_kernel(float* __restrict__ idx_out_f) {
    int n = (blockIdx.x * blockDim.x + threadIdx.x) >> 5;
    int lane = threadIdx.x & 31;
    int4 cd = g_candi[n];
    const float4* zr = (const float4*)(g_zt + (size_t)n * CDIM);
    const float4* c0 = (const float4*)(g_cn + (size_t)cd.x * CDIM);
    const float4* c1 = (const float4*)(g_cn + (size_t)cd.y * CDIM);
    const float4* c2 = (const float4*)(g_cn + (size_t)cd.z * CDIM);
    float d0 = 0.0f, d1 = 0.0f, d2 = 0.0f;
#pragma unroll
    for (int i = 0; i < 2; i++) {
        float4 zv = zr[lane + i * 32];
        float4 a  = c0[lane + i * 32];
        float4 b  = c1[lane + i * 32];
        float4 c  = c2[lane + i * 32];
        d0 = fmaf(zv.x, a.x, fmaf(zv.y, a.y, fmaf(zv.z, a.z, fmaf(zv.w, a.w, d0))));
        d1 = fmaf(zv.x, b.x, fmaf(zv.y, b.y, fmaf(zv.z, b.z, fmaf(zv.w, b.w, d1))));
        d2 = fmaf(zv.x, c.x, fmaf(zv.y, c.y, fmaf(zv.z, c.z, fmaf(zv.w, c.w, d2))));
    }
#pragma unroll
    for (int off = 16; off; off >>= 1) {
        d0 += __shfl_xor_sync(0xffffffffu, d0, off);
        d1 += __shfl_xor_sync(0xffffffffu, d1, off);
        d2 += __shfl_xor_sync(0xffffffffu, d2, off);
    }
    if (lane == 0) {
        float bv = d0; int bi = cd.x;
        if (better(d1, cd.y, bv, bi)) { bv = d1; bi = cd.y; }
        if (better(d2, cd.z, bv, bi)) { bv = d2; bi = cd.z; }
        g_idx[n] = bi;
        idx_out_f[n] = (float)bi;
    }
}

// ---------------------------------------------------------------------------
// Gather + straight-through output + loss, fully coalesced via smem transpose.
// CTA handles one (b, 32-wide hw block). Last CTA finalizes the loss scalar.
__global__ void gather_loss_kernel(const float* __restrict__ z,
                                   const float* __restrict__ E,
                                   float* __restrict__ out) {
    __shared__ float q[256 * 33];
    int tid = threadIdx.x;
    int wid = tid >> 5, lane = tid & 31;
    int b = blockIdx.x >> 5;
    int hw0 = (blockIdx.x & 31) * 32;

    // phase 1: gather codebook rows (coalesced) into transposed smem tile
#pragma unroll
    for (int r = 0; r < 4; r++) {
        int hh = wid * 4 + r;
        int n  = b * 1024 + hw0 + hh;
        int k  = g_idx[n];
        const float4* Er = (const float4*)(E + (size_t)k * CDIM);
#pragma unroll
        for (int i = 0; i < 2; i++) {
            int c4 = (lane + i * 32) * 4;
            float4 v = Er[lane + i * 32];
            q[(c4 + 0) * 33 + hh] = v.x;
            q[(c4 + 1) * 33 + hh] = v.y;
            q[(c4 + 2) * 33 + hh] = v.z;
            q[(c4 + 3) * 33 + hh] = v.w;
        }
    }
    __syncthreads();

    // phase 2: coalesced z read / out write along hw; accumulate loss
    float d2sum = 0.0f;
    size_t gbase = (size_t)b * 262144 + hw0 + lane;
#pragma unroll 4
    for (int i = 0; i < 32; i++) {
        int c = wid * 32 + i;
        float qv = q[c * 33 + lane];
        float zv = z[gbase + (size_t)c * 1024];
        float d  = qv - zv;
        out[gbase + (size_t)c * 1024] = zv + d;
        d2sum = fmaf(d, d, d2sum);
    }
#pragma unroll
    for (int off = 16; off; off >>= 1)
        d2sum += __shfl_xor_sync(0xffffffffu, d2sum, off);
    __shared__ float ws[8];
    if (lane == 0) ws[wid] = d2sum;
    __syncthreads();
    if (wid == 0) {
        float s = (lane < 8) ? ws[lane] : 0.0f;
#pragma unroll
        for (int off = 4; off; off >>= 1)
            s += __shfl_xor_sync(0xffffffffu, s, off);
        if (lane == 0) {
            atomicAdd(&g_acc, (double)s);
            __threadfence();
            unsigned int t = atomicAdd(&g_ticket, 1u);
            if (t == gridDim.x - 1) {
                // last CTA: all g_acc contributions visible (fence-before-ticket)
                double m = g_acc / (double)OUT_ELEMS;
                out[OUT_ELEMS] = (float)(0.25 * m + m);
            }
        }
    }
}

// ---------------------------------------------------------------------------
extern "C" void kernel_launch(void* const* d_in, const int* in_sizes, int n_in,
                              void* d_out, int out_size) {
    const float* z = (const float*)d_in[0];
    const float* E = (const float*)d_in[1];
    float* out = (float*)d_out;

    cudaFuncSetAttribute(vq_mma_kernel,
                         cudaFuncAttributeMaxDynamicSharedMemorySize, SMEM_BYTES);

    split_z_kernel<<<dim3(32, 8, 32), 256>>>(z);
    norm_split_codebook<<<K_CODES / 8, 256>>>(E);
    vq_mma_kernel<<<NQ / MT, THREADS, SMEM_BYTES>>>();
    fixup_kernel<<<NQ / 8, 256>>>(out + OUT_ELEMS + 1);
    gather_loss_kernel<<<1024, 256>>>(z, E, out);
}